// round 5
// baseline (speedup 1.0000x reference)
#include <cuda_runtime.h>

#define BB 1024
#define DD 128
#define TT 256
#define HH 64
#define GG 256  // 4*H

typedef unsigned long long ull;

// 256 MB scratch for xp0 = xt @ w_ih0^T + (b_ih0 + b_hh0), layout [B][T][4H]
__device__ float g_xp0[(size_t)BB * TT * GG];

// ---------------------------------------------------------------------------
// f32x2 helpers
// ---------------------------------------------------------------------------
__device__ __forceinline__ void ffma2(ull& d, ull a, ull b) {
    asm("fma.rn.f32x2 %0, %1, %2, %0;" : "+l"(d) : "l"(a), "l"(b));
}
__device__ __forceinline__ float2 u2f(ull u) {
    float2 r;
    r.x = __uint_as_float((unsigned)(u & 0xffffffffULL));
    r.y = __uint_as_float((unsigned)(u >> 32));
    return r;
}

// ---------------------------------------------------------------------------
// Activations
// ---------------------------------------------------------------------------
__device__ __forceinline__ float sigm(float x) {
    return __fdividef(1.0f, 1.0f + __expf(-x));
}
__device__ __forceinline__ float tanh_acc(float x) {
    float a = fabsf(x);
    float e = __expf(-2.0f * a);
    float r = (1.0f - e) * __fdividef(1.0f, 1.0f + e);
    return copysignf(r, x);
}

// ---------------------------------------------------------------------------
// Kernel 1: xp0[b, t, g] = sum_d x[b, d, t] * w_ih0[g, d] + bias[g]
// Grid: 1024 CTAs (one b each), 4 t-tiles x 2 d-chunks. Block: 256.
// smem: wt[64][260] + xd[64][64] dup float2 = 99328 B -> 2 CTAs/SM.
// ---------------------------------------------------------------------------
__global__ __launch_bounds__(256) void k_inproj(
    const float* __restrict__ x,
    const float* __restrict__ w_ih0,
    const float* __restrict__ b_ih0,
    const float* __restrict__ b_hh0)
{
    extern __shared__ float sm[];
    float* wt = sm;              // [64][260]
    float* xd = sm + 64 * 260;   // [64][64] of float2 {v, v}

    const int tid = threadIdx.x;
    const int b   = blockIdx.x;

    const int tx = tid & 31;   // g chunks: tx*4 and 128+tx*4
    const int ty = tid >> 5;   // t chunks: ty*4 and 32+ty*4

    // bias (b_ih0 + b_hh0) for this thread's 8 g's
    const float4* bi4 = (const float4*)b_ih0;
    const float4* bh4 = (const float4*)b_hh0;
    float4 bia = bi4[tx],      bha = bh4[tx];
    float4 bib = bi4[32 + tx], bhb = bh4[32 + tx];
    float blo[4] = {bia.x + bha.x, bia.y + bha.y, bia.z + bha.z, bia.w + bha.w};
    float bhi[4] = {bib.x + bhb.x, bib.y + bhb.y, bib.z + bhb.z, bib.w + bhb.w};

    const float4* w4 = (const float4*)w_ih0;  // [256 g][32 quads]

    for (int tt = 0; tt < 4; tt++) {
        const int t0 = tt * 64;

        ull acc[8][4];
        #pragma unroll
        for (int a = 0; a < 8; a++)
            #pragma unroll
            for (int e = 0; e < 4; e++) acc[a][e] = 0ULL;

        for (int c = 0; c < 2; c++) {
            __syncthreads();
            // Load w chunk: wt[dl][g], dl = d - 64c
            #pragma unroll
            for (int i = 0; i < 16; i++) {
                int idx = tid + i * 256;        // 0..4095
                int g   = idx >> 4;
                int jq  = idx & 15;
                float4 v = w4[g * 32 + c * 16 + jq];
                wt[(4 * jq + 0) * 260 + g] = v.x;
                wt[(4 * jq + 1) * 260 + g] = v.y;
                wt[(4 * jq + 2) * 260 + g] = v.z;
                wt[(4 * jq + 3) * 260 + g] = v.w;
            }
            // Load x chunk duplicated
            {
                const float* xb = x + (size_t)b * DD * TT + (size_t)c * 64 * TT + t0;
                int t = tid & 63, d0 = tid >> 6;
                #pragma unroll
                for (int d = d0; d < 64; d += 4) {
                    float v = xb[d * TT + t];
                    ((float2*)xd)[d * 64 + t] = make_float2(v, v);
                }
            }
            __syncthreads();

            #pragma unroll 4
            for (int d = 0; d < 64; d++) {
                ulonglong2 x01 = *(const ulonglong2*)&xd[(d * 64 + ty * 4) * 2];
                ulonglong2 x23 = *(const ulonglong2*)&xd[(d * 64 + ty * 4 + 2) * 2];
                ulonglong2 x45 = *(const ulonglong2*)&xd[(d * 64 + 32 + ty * 4) * 2];
                ulonglong2 x67 = *(const ulonglong2*)&xd[(d * 64 + 32 + ty * 4 + 2) * 2];
                ulonglong2 wa = *(const ulonglong2*)&wt[d * 260 + tx * 4];
                ulonglong2 wb = *(const ulonglong2*)&wt[d * 260 + 128 + tx * 4];
                ull xv[8] = {x01.x, x01.y, x23.x, x23.y, x45.x, x45.y, x67.x, x67.y};
                ull wp[4] = {wa.x, wa.y, wb.x, wb.y};
                #pragma unroll
                for (int a = 0; a < 8; a++)
                    #pragma unroll
                    for (int e = 0; e < 4; e++)
                        ffma2(acc[a][e], xv[a], wp[e]);
            }
        }

        #pragma unroll
        for (int a = 0; a < 8; a++) {
            int t = (a < 4) ? (ty * 4 + a) : (32 + ty * 4 + (a - 4));
            float* row = g_xp0 + ((size_t)b * TT + t0 + t) * GG;
            float2 p0 = u2f(acc[a][0]), p1 = u2f(acc[a][1]);
            float2 p2 = u2f(acc[a][2]), p3 = u2f(acc[a][3]);
            float4 lo = make_float4(p0.x + blo[0], p0.y + blo[1],
                                    p1.x + blo[2], p1.y + blo[3]);
            float4 hi = make_float4(p2.x + bhi[0], p2.y + bhi[1],
                                    p3.x + bhi[2], p3.y + bhi[3]);
            *(float4*)(row + tx * 4)       = lo;
            *(float4*)(row + 128 + tx * 4) = hi;
        }
    }
}

// ---------------------------------------------------------------------------
// Kernel 2: fused 2-layer LSTM recurrence + head. 128 CTAs x 8 batch rows.
// 256 threads; thread = (g-pair gp = tid&127, k-half kh = tid>>7).
// Each h-broadcast LDS feeds 4 FFMA2 (2 gates) -> halved crossbar wavefronts.
// smem floats: W0|W1|W2 [2eo][16 k4][128 gp] float4 (64KB each) |
//              h0f[8][64] | h1f[8][64] | gsm[2 kh][8 b][256 g]  = 217088 B
// ---------------------------------------------------------------------------
#define W0OFF 0
#define W1OFF 16384
#define W2OFF 32768
#define H0OFF 49152
#define H1OFF 49664
#define GSOFF 50176
#define SMFL  54272

__global__ __launch_bounds__(256) void k_lstm(
    const float* __restrict__ w_hh0,
    const float* __restrict__ w_ih1,
    const float* __restrict__ b_ih1,
    const float* __restrict__ b_hh1,
    const float* __restrict__ w_hh1,
    const float* __restrict__ w_fc,
    const float* __restrict__ b_fc,
    float* __restrict__ out)
{
    extern __shared__ float sm[];
    float* w0q = sm + W0OFF;
    float* w1q = sm + W1OFF;
    float* w2q = sm + W2OFF;
    float* h0f = sm + H0OFF;
    float* h1f = sm + H1OFF;
    float* gsm = sm + GSOFF;

    const int tid = threadIdx.x;
    const int b0  = blockIdx.x * 8;

    const int gp = tid & 127;     // g-pair: gates 2gp, 2gp+1
    const int kh = tid >> 7;      // k-half: k4 in [8kh, 8kh+8)
    const int g0 = gp * 2;

    // Repack [256 g][64 k] weights -> [eo][k4][gp] float4
    {
        const float4* a4 = (const float4*)w_hh0;
        const float4* b4 = (const float4*)w_ih1;
        const float4* c4 = (const float4*)w_hh1;
        #pragma unroll
        for (int i = 0; i < 16; i++) {
            int idx = tid + i * 256;          // 0..4095
            int p   = idx & 127;
            int k4  = (idx >> 7) & 15;
            int eo  = idx >> 11;
            int dst = eo * 2048 + k4 * 128 + p;
            int src = (2 * p + eo) * 16 + k4;
            ((float4*)w0q)[dst] = a4[src];
            ((float4*)w1q)[dst] = b4[src];
            ((float4*)w2q)[dst] = c4[src];
        }
    }
    for (int i = tid; i < 512; i += 256) { h0f[i] = 0.0f; h1f[i] = 0.0f; }

    const float bias1e = b_ih1[g0] + b_hh1[g0];
    const float bias1o = b_ih1[g0 + 1] + b_hh1[g0 + 1];

    // Cell ownership for elementwise phases
    const int ch = tid & 63;
    const int cb = tid >> 6;      // 0..3; handles (ch,cb) and (ch,cb+4)
    float c0a = 0.0f, c0b = 0.0f, c1a = 0.0f, c1b = 0.0f;

    __syncthreads();

    const float* xpb = g_xp0 + (size_t)b0 * TT * GG + g0;
    float* gst = gsm + kh * 2048 + g0;   // store base: + b*256

    // Prefetch xp for t=0 (kh==0 warps only)
    float2 xv[8];
    if (kh == 0) {
        #pragma unroll
        for (int b = 0; b < 8; b++)
            xv[b] = *(const float2*)(xpb + (size_t)b * TT * GG);
    }

    for (int t = 0; t < TT; t++) {
        // ---- Phase A: gates0 = xp0[:, t, :] + h0 @ w_hh0^T ----
        ull ae[8], ao[8];
        #pragma unroll
        for (int b = 0; b < 8; b++) { ae[b] = 0ULL; ao[b] = 0ULL; }

        #pragma unroll
        for (int k4 = 0; k4 < 8; k4++) {
            int kk = kh * 8 + k4;
            ulonglong2 we = *(const ulonglong2*)&w0q[(kk * 128 + gp) * 4];
            ulonglong2 wo = *(const ulonglong2*)&w0q[(2048 + kk * 128 + gp) * 4];
            #pragma unroll
            for (int b = 0; b < 8; b++) {
                ulonglong2 h = *(const ulonglong2*)&h0f[b * 64 + kk * 4];
                ffma2(ae[b], h.x, we.x);
                ffma2(ae[b], h.y, we.y);
                ffma2(ao[b], h.x, wo.x);
                ffma2(ao[b], h.y, wo.y);
            }
        }
        #pragma unroll
        for (int b = 0; b < 8; b++) {
            float2 pe = u2f(ae[b]), po = u2f(ao[b]);
            float ve = pe.x + pe.y, vo = po.x + po.y;
            if (kh == 0) { ve += xv[b].x; vo += xv[b].y; }
            *(float2*)(gst + b * 256) = make_float2(ve, vo);
        }
        __syncthreads();  // (1)

        // ---- layer-0 cell updates (2 per thread) ----
        {
            const float* gA = gsm + cb * 256;
            const float* gB = gsm + 2048 + cb * 256;
            float i0 = gA[ch] + gB[ch];
            float f0 = gA[64 + ch] + gB[64 + ch];
            float g0v = gA[128 + ch] + gB[128 + ch];
            float o0 = gA[192 + ch] + gB[192 + ch];
            float i1 = gA[1024 + ch] + gB[1024 + ch];
            float f1 = gA[1024 + 64 + ch] + gB[1024 + 64 + ch];
            float g1v = gA[1024 + 128 + ch] + gB[1024 + 128 + ch];
            float o1 = gA[1024 + 192 + ch] + gB[1024 + 192 + ch];
            c0a = sigm(f0) * c0a + sigm(i0) * tanh_acc(g0v);
            c0b = sigm(f1) * c0b + sigm(i1) * tanh_acc(g1v);
            h0f[cb * 64 + ch]       = sigm(o0) * tanh_acc(c0a);
            h0f[(cb + 4) * 64 + ch] = sigm(o1) * tanh_acc(c0b);
        }
        __syncthreads();  // (2)

        // Prefetch xp for next t (hidden under phase C)
        if (kh == 0) {
            int tn = (t + 1 < TT) ? t + 1 : TT - 1;
            #pragma unroll
            for (int b = 0; b < 8; b++)
                xv[b] = *(const float2*)(xpb + ((size_t)b * TT + tn) * GG);
        }

        // ---- Phase C: gates1 = bias1 + h0 @ w_ih1^T + h1 @ w_hh1^T ----
        #pragma unroll
        for (int b = 0; b < 8; b++) { ae[b] = 0ULL; ao[b] = 0ULL; }

        #pragma unroll
        for (int k4 = 0; k4 < 8; k4++) {
            int kk = kh * 8 + k4;
            ulonglong2 w1e = *(const ulonglong2*)&w1q[(kk * 128 + gp) * 4];
            ulonglong2 w1o = *(const ulonglong2*)&w1q[(2048 + kk * 128 + gp) * 4];
            ulonglong2 w2e = *(const ulonglong2*)&w2q[(kk * 128 + gp) * 4];
            ulonglong2 w2o = *(const ulonglong2*)&w2q[(2048 + kk * 128 + gp) * 4];
            #pragma unroll
            for (int b = 0; b < 8; b++) {
                ulonglong2 ha = *(const ulonglong2*)&h0f[b * 64 + kk * 4];
                ulonglong2 hb = *(const ulonglong2*)&h1f[b * 64 + kk * 4];
                ffma2(ae[b], ha.x, w1e.x);
                ffma2(ae[b], ha.y, w1e.y);
                ffma2(ao[b], ha.x, w1o.x);
                ffma2(ao[b], ha.y, w1o.y);
                ffma2(ae[b], hb.x, w2e.x);
                ffma2(ae[b], hb.y, w2e.y);
                ffma2(ao[b], hb.x, w2o.x);
                ffma2(ao[b], hb.y, w2o.y);
            }
        }
        #pragma unroll
        for (int b = 0; b < 8; b++) {
            float2 pe = u2f(ae[b]), po = u2f(ao[b]);
            float ve = pe.x + pe.y, vo = po.x + po.y;
            if (kh == 0) { ve += bias1e; vo += bias1o; }
            *(float2*)(gst + b * 256) = make_float2(ve, vo);
        }
        __syncthreads();  // (3)

        // ---- layer-1 cell updates ----
        {
            const float* gA = gsm + cb * 256;
            const float* gB = gsm + 2048 + cb * 256;
            float i0 = gA[ch] + gB[ch];
            float f0 = gA[64 + ch] + gB[64 + ch];
            float g0v = gA[128 + ch] + gB[128 + ch];
            float o0 = gA[192 + ch] + gB[192 + ch];
            float i1 = gA[1024 + ch] + gB[1024 + ch];
            float f1 = gA[1024 + 64 + ch] + gB[1024 + 64 + ch];
            float g1v = gA[1024 + 128 + ch] + gB[1024 + 128 + ch];
            float o1 = gA[1024 + 192 + ch] + gB[1024 + 192 + ch];
            c1a = sigm(f0) * c1a + sigm(i0) * tanh_acc(g0v);
            c1b = sigm(f1) * c1b + sigm(i1) * tanh_acc(g1v);
            h1f[cb * 64 + ch]       = sigm(o0) * tanh_acc(c1a);
            h1f[(cb + 4) * 64 + ch] = sigm(o1) * tanh_acc(c1b);
        }
        __syncthreads();  // (4)
    }

    // ---- Head: scores[b, :] = hT @ w_fc^T + b_fc ----
    float* wfct = w0q;  // reuse (fully synced): [k][o], 64x128
    for (int i = tid; i < 128 * 64; i += 256) {
        int o = i >> 6, k = i & 63;
        wfct[k * 128 + o] = w_fc[i];
    }
    __syncthreads();

    #pragma unroll
    for (int q = 0; q < 4; q++) {
        int p  = tid + q * 256;   // 0..1023
        int bo = p >> 7;          // batch row 0..7
        int o  = p & 127;         // output feature
        float acc = b_fc[o];
        #pragma unroll 4
        for (int k = 0; k < 64; k++)
            acc += h1f[bo * 64 + k] * wfct[k * 128 + o];
        out[(size_t)(b0 + bo) * 128 + o] = acc;
    }
}

// ---------------------------------------------------------------------------
// Launch
// ---------------------------------------------------------------------------
extern "C" void kernel_launch(void* const* d_in, const int* in_sizes, int n_in,
                              void* d_out, int out_size)
{
    const float* x     = (const float*)d_in[0];
    const float* w_ih0 = (const float*)d_in[1];
    const float* w_hh0 = (const float*)d_in[2];
    const float* b_ih0 = (const float*)d_in[3];
    const float* b_hh0 = (const float*)d_in[4];
    const float* w_ih1 = (const float*)d_in[5];
    const float* w_hh1 = (const float*)d_in[6];
    const float* b_ih1 = (const float*)d_in[7];
    const float* b_hh1 = (const float*)d_in[8];
    const float* w_fc  = (const float*)d_in[9];
    const float* b_fc  = (const float*)d_in[10];
    float* out = (float*)d_out;

    const int smem1 = (64 * 260 + 64 * 64 * 2) * 4;  // 99328
    const int smem2 = SMFL * 4;                      // 217088

    cudaFuncSetAttribute(k_inproj, cudaFuncAttributeMaxDynamicSharedMemorySize, smem1);
    cudaFuncSetAttribute(k_lstm,   cudaFuncAttributeMaxDynamicSharedMemorySize, smem2);

    k_inproj<<<1024, 256, smem1>>>(x, w_ih0, b_ih0, b_hh0);
    k_lstm<<<128, 256, smem2>>>(w_hh0, w_ih1, b_ih1, b_hh1, w_hh1, w_fc, b_fc, out);
}